// round 1
// baseline (speedup 1.0000x reference)
#include <cuda_runtime.h>
#include <cstdint>

#define DEV static __device__ __forceinline__

static constexpr int B_ = 4, N_ = 256, D_ = 128, L_ = 3, BN = 1024;

// ---------------- scratch (device globals; no allocation allowed) ----------------
__device__ float g_P[BN * 384];          // per-layer projections: [Pi | Pj | Pn]
__device__ float g_aggH[2][BN * D_];     // j-split partial aggregations
__device__ float g_rs[BN];               // rowsum(adj)
__device__ float g_Wc[L_][D_ * D_];      // ew2 @ nw1b
__device__ float g_cb[L_][D_];           // eb2 @ nw1b
__device__ float g_adj2[B_ * N_ * 2 * N_]; // [b][j][2*i] duplicated adjacency

// ---------------- f32x2 helpers ----------------
DEV unsigned long long pk(float lo, float hi) {
    unsigned long long r;
    asm("mov.b64 %0,{%1,%2};" : "=l"(r) : "f"(lo), "f"(hi));
    return r;
}
DEV void upk(unsigned long long v, float& lo, float& hi) {
    asm("mov.b64 {%0,%1},%2;" : "=f"(lo), "=f"(hi) : "l"(v));
}
DEV unsigned long long add2(unsigned long long a, unsigned long long b) {
    unsigned long long r;
    asm("add.rn.f32x2 %0,%1,%2;" : "=l"(r) : "l"(a), "l"(b));
    return r;
}
DEV unsigned long long fma2(unsigned long long a, unsigned long long b, unsigned long long c) {
    unsigned long long r;
    asm("fma.rn.f32x2 %0,%1,%2,%3;" : "=l"(r) : "l"(a), "l"(b), "l"(c));
    return r;
}
DEV unsigned long long relu2(unsigned long long v) {
    float lo, hi;
    upk(v, lo, hi);
    lo = fmaxf(lo, 0.f);
    hi = fmaxf(hi, 0.f);
    return pk(lo, hi);
}

// ---------------- setup kernels ----------------
// duplicate adjacency into [b][j][2i] layout for broadcast-friendly smem staging
__global__ void k_setup_adj(const float* __restrict__ adj) {
    int idx = blockIdx.x * blockDim.x + threadIdx.x;   // j fastest
    int j = idx & 255, i = (idx >> 8) & 255, b = idx >> 16;
    float v = adj[idx];
    float* dst = g_adj2 + ((b * N_ + j) * 2 * N_) + 2 * i;
    dst[0] = v;
    dst[1] = v;
}

__global__ void k_rowsum(const float* __restrict__ adj) {
    int w = (blockIdx.x * blockDim.x + threadIdx.x) >> 5;  // one warp per row
    int lane = threadIdx.x & 31;
    const float* row = adj + w * N_;
    float s = 0.f;
#pragma unroll
    for (int j = lane; j < N_; j += 32) s += row[j];
#pragma unroll
    for (int o = 16; o; o >>= 1) s += __shfl_xor_sync(~0u, s, o);
    if (!lane) g_rs[w] = s;
}

// Wc[l] = ew2[l] @ nw1[l, D:, :],  cb[l] = eb2[l] @ nw1[l, D:, :]
__global__ void k_wc(const float* __restrict__ ew2, const float* __restrict__ eb2,
                     const float* __restrict__ nw1) {
    int l = blockIdx.y, rblk = blockIdx.x;
    int k = threadIdx.x;  // 128
    const float* w2 = ew2 + l * D_ * D_ + rblk * 16 * D_;
    const float* n1b = nw1 + l * 2 * D_ * D_ + D_ * D_;
    const float* b2 = eb2 + l * D_;
    float acc[16];
#pragma unroll
    for (int r = 0; r < 16; r++) acc[r] = 0.f;
    float accb = 0.f;
    for (int m = 0; m < D_; m++) {
        float wv = n1b[m * D_ + k];
#pragma unroll
        for (int r = 0; r < 16; r++) acc[r] = fmaf(w2[r * D_ + m], wv, acc[r]);
        if (rblk == 0) accb = fmaf(b2[m], wv, accb);
    }
#pragma unroll
    for (int r = 0; r < 16; r++) g_Wc[l][(rblk * 16 + r) * D_ + k] = acc[r];
    if (rblk == 0) g_cb[l][k] = accb;
}

// ---------------- packed-f32x2 micro GEMM ----------------
// ATs: [128 k][20] transposed A tile (16 rows, padded).  Ws: [128 k][128 cols].
// Thread (cg = tid&63, rh = tid>>6) computes rows rh*8..rh*8+7 x cols 2cg,2cg+1.
// acc[rp][c] packs rows (rh*8+2rp, rh*8+2rp+1) of column 2cg+c.
DEV void micro_gemm(const float* __restrict__ ATs, const float* __restrict__ Ws,
                    int cg, int rh, unsigned long long acc[4][2]) {
    const float* ap = ATs + rh * 8;
    const float* wp = Ws + 2 * cg;
#pragma unroll 8
    for (int k = 0; k < 128; k++) {
        ulonglong2 a01 = *(const ulonglong2*)(ap + k * 20);      // row pairs 0,1
        ulonglong2 a23 = *(const ulonglong2*)(ap + k * 20 + 4);  // row pairs 2,3
        float2 wv = *(const float2*)(wp + k * 128);
        unsigned long long w0 = pk(wv.x, wv.x);
        unsigned long long w1 = pk(wv.y, wv.y);
        acc[0][0] = fma2(a01.x, w0, acc[0][0]);
        acc[0][1] = fma2(a01.x, w1, acc[0][1]);
        acc[1][0] = fma2(a01.y, w0, acc[1][0]);
        acc[1][1] = fma2(a01.y, w1, acc[1][1]);
        acc[2][0] = fma2(a23.x, w0, acc[2][0]);
        acc[2][1] = fma2(a23.x, w1, acc[2][1]);
        acc[3][0] = fma2(a23.y, w0, acc[3][0]);
        acc[3][1] = fma2(a23.y, w1, acc[3][1]);
    }
}

// ---------------- K1: projections P = x @ [ew1a | ew1b | nw1a] (+biases) ----------------
// grid (64 rowblocks, 3 colblocks), 128 threads, dynamic smem = Ws(64KB) + ATs(10KB)
__global__ void k_proj(const float* __restrict__ x, const float* __restrict__ ew1,
                       const float* __restrict__ nw1, const float* __restrict__ eb1,
                       const float* __restrict__ nb1, int l) {
    extern __shared__ float sm[];
    float* Ws = sm;            // 16384 floats
    float* ATs = sm + 16384;   // 2560 floats
    int rb = blockIdx.x, cblk = blockIdx.y;
    int tid = threadIdx.x;

    const float* W;
    const float* bias = nullptr;
    if (cblk == 0) { W = ew1 + l * 2 * D_ * D_;            bias = eb1 + l * D_; }
    else if (cblk == 1) { W = ew1 + l * 2 * D_ * D_ + D_ * D_; }
    else { W = nw1 + l * 2 * D_ * D_;                      bias = nb1 + l * D_; }

    const float* Arows = x + rb * 16 * D_;
    for (int idx = tid; idx < 16 * 128; idx += 128) {
        int r = idx >> 7, k = idx & 127;
        ATs[k * 20 + r] = Arows[idx];
    }
    for (int idx = tid; idx < 4096; idx += 128)
        ((float4*)Ws)[idx] = ((const float4*)W)[idx];
    __syncthreads();

    int cg = tid & 63, rh = tid >> 6;
    unsigned long long acc[4][2] = {};
    micro_gemm(ATs, Ws, cg, rh, acc);

    float b0 = 0.f, b1 = 0.f;
    if (bias) { b0 = bias[2 * cg]; b1 = bias[2 * cg + 1]; }
    float* Pout = g_P + (rb * 16 + rh * 8) * 384 + cblk * 128 + 2 * cg;
#pragma unroll
    for (int rp = 0; rp < 4; rp++) {
        float v00, v10, v01, v11;
        upk(acc[rp][0], v00, v10);
        upk(acc[rp][1], v01, v11);
        Pout[(2 * rp) * 384 + 0] = v00 + b0;
        Pout[(2 * rp) * 384 + 1] = v01 + b1;
        Pout[(2 * rp + 1) * 384 + 0] = v10 + b0;
        Pout[(2 * rp + 1) * 384 + 1] = v11 + b1;
    }
}

// ---------------- K2: aggH[jh][b,i,:] = sum_{j in half} adj[b,i,j]*relu(Pi[b,i]+Pj[b,j]) ----------------
// grid (64 = b*16+iblk, 2 = jhalf), 128 threads (4 warps x 4 i's each; lane = 4 d's)
__global__ void k_agg() {
    extern __shared__ float sm[];
    float* Pjs = sm;             // [128 j][128 d]  64KB
    float* adj2s = sm + 16384;   // [128 j][32]     16KB (duplicated adj pairs)
    int b = blockIdx.x >> 4, iblk = blockIdx.x & 15, jh = blockIdx.y;
    int tid = threadIdx.x;
    int ibase = iblk * 16, jbase = jh * 128;

    for (int idx = tid; idx < 4096; idx += 128) {
        int jj = idx >> 5, d4 = idx & 31;
        ((float4*)(Pjs + jj * 128))[d4] =
            *(const float4*)(g_P + (b * 256 + jbase + jj) * 384 + 128 + d4 * 4);
    }
    for (int idx = tid; idx < 1024; idx += 128) {
        int jj = idx >> 3, c4 = idx & 7;
        ((float4*)(adj2s + jj * 32))[c4] =
            *(const float4*)(g_adj2 + (b * 256 + jbase + jj) * 512 + 2 * ibase + c4 * 4);
    }
    __syncthreads();

    int lane = tid & 31, w = tid >> 5;
    int d0 = lane * 4;
    unsigned long long xi[4][2];
#pragma unroll
    for (int q = 0; q < 4; q++) {
        ulonglong2 v = *(const ulonglong2*)(g_P + (b * 256 + ibase + w * 4 + q) * 384 + d0);
        xi[q][0] = v.x;
        xi[q][1] = v.y;
    }
    unsigned long long acc[4][2] = {};
    const float* pj = Pjs + d0;
    const float* ad = adj2s + w * 8;
#pragma unroll 4
    for (int jj = 0; jj < 128; jj++) {
        ulonglong2 xj = *(const ulonglong2*)(pj + jj * 128);
        ulonglong2 a01 = *(const ulonglong2*)(ad + jj * 32);      // dup pairs i0,i1
        ulonglong2 a23 = *(const ulonglong2*)(ad + jj * 32 + 4);  // dup pairs i2,i3
        unsigned long long t;
        t = relu2(add2(xi[0][0], xj.x)); acc[0][0] = fma2(t, a01.x, acc[0][0]);
        t = relu2(add2(xi[0][1], xj.y)); acc[0][1] = fma2(t, a01.x, acc[0][1]);
        t = relu2(add2(xi[1][0], xj.x)); acc[1][0] = fma2(t, a01.y, acc[1][0]);
        t = relu2(add2(xi[1][1], xj.y)); acc[1][1] = fma2(t, a01.y, acc[1][1]);
        t = relu2(add2(xi[2][0], xj.x)); acc[2][0] = fma2(t, a23.x, acc[2][0]);
        t = relu2(add2(xi[2][1], xj.y)); acc[2][1] = fma2(t, a23.x, acc[2][1]);
        t = relu2(add2(xi[3][0], xj.x)); acc[3][0] = fma2(t, a23.y, acc[3][0]);
        t = relu2(add2(xi[3][1], xj.y)); acc[3][1] = fma2(t, a23.y, acc[3][1]);
    }
#pragma unroll
    for (int q = 0; q < 4; q++) {
        float* o = g_aggH[jh] + (b * 256 + ibase + w * 4 + q) * 128 + d0;
        ulonglong2 st;
        st.x = acc[q][0];
        st.y = acc[q][1];
        *(ulonglong2*)o = st;
    }
}

// ---------------- K3: nh = relu(Pn + aggH@Wc + rs*cb); x += nh@nw2 + nb2 ----------------
// grid 64 (16 rows each), 128 threads; smem = Ws(64KB)+ATs(10KB)+NTs(10KB)
__global__ void k_node(float* __restrict__ x, const float* __restrict__ nw2,
                       const float* __restrict__ nb2, int l) {
    extern __shared__ float sm[];
    float* Ws = sm;
    float* ATs = sm + 16384;
    float* NTs = sm + 16384 + 2560;
    int rb = blockIdx.x;
    int tid = threadIdx.x;

    const float* Wc = g_Wc[l];
    for (int idx = tid; idx < 4096; idx += 128)
        ((float4*)Ws)[idx] = ((const float4*)Wc)[idx];
    for (int idx = tid; idx < 2048; idx += 128) {
        int r = idx >> 7, k = idx & 127;
        int row = rb * 16 + r;
        ATs[k * 20 + r] = g_aggH[0][row * 128 + k] + g_aggH[1][row * 128 + k];
    }
    __syncthreads();

    int cg = tid & 63, rh = tid >> 6;
    unsigned long long acc[4][2] = {};
    micro_gemm(ATs, Ws, cg, rh, acc);

    float cb0 = g_cb[l][2 * cg], cb1 = g_cb[l][2 * cg + 1];
#pragma unroll
    for (int rp = 0; rp < 4; rp++) {
        int r0 = rh * 8 + 2 * rp;
        int row0 = rb * 16 + r0;
        float2 pn0 = *(const float2*)(g_P + row0 * 384 + 256 + 2 * cg);
        float2 pn1 = *(const float2*)(g_P + (row0 + 1) * 384 + 256 + 2 * cg);
        float rs0 = g_rs[row0], rs1 = g_rs[row0 + 1];
        float v00, v10, v01, v11;
        upk(acc[rp][0], v00, v10);
        upk(acc[rp][1], v01, v11);
        v00 = fmaxf(fmaf(rs0, cb0, v00 + pn0.x), 0.f);
        v01 = fmaxf(fmaf(rs0, cb1, v01 + pn0.y), 0.f);
        v10 = fmaxf(fmaf(rs1, cb0, v10 + pn1.x), 0.f);
        v11 = fmaxf(fmaf(rs1, cb1, v11 + pn1.y), 0.f);
        NTs[(2 * cg) * 20 + r0] = v00;
        NTs[(2 * cg + 1) * 20 + r0] = v01;
        NTs[(2 * cg) * 20 + r0 + 1] = v10;
        NTs[(2 * cg + 1) * 20 + r0 + 1] = v11;
    }
    __syncthreads();  // all Ws reads + NTs writes done

    const float* W2 = nw2 + l * D_ * D_;
    for (int idx = tid; idx < 4096; idx += 128)
        ((float4*)Ws)[idx] = ((const float4*)W2)[idx];
    __syncthreads();

    unsigned long long acc2[4][2] = {};
    micro_gemm(NTs, Ws, cg, rh, acc2);

    float b0 = nb2[l * D_ + 2 * cg], b1 = nb2[l * D_ + 2 * cg + 1];
#pragma unroll
    for (int rp = 0; rp < 4; rp++) {
        int r0 = rh * 8 + 2 * rp;
        int row0 = rb * 16 + r0;
        float v00, v10, v01, v11;
        upk(acc2[rp][0], v00, v10);
        upk(acc2[rp][1], v01, v11);
        float2* x0 = (float2*)(x + row0 * D_ + 2 * cg);
        float2* x1 = (float2*)(x + (row0 + 1) * D_ + 2 * cg);
        float2 o0 = *x0, o1 = *x1;
        o0.x += v00 + b0;
        o0.y += v01 + b1;
        o1.x += v10 + b0;
        o1.y += v11 + b1;
        *x0 = o0;
        *x1 = o1;
    }
}

// ---------------- launch ----------------
extern "C" void kernel_launch(void* const* d_in, const int* in_sizes, int n_in,
                              void* d_out, int out_size) {
    const float* nf  = (const float*)d_in[0];
    const float* adj = (const float*)d_in[1];
    const float* ew1 = (const float*)d_in[2];
    const float* eb1 = (const float*)d_in[3];
    const float* ew2 = (const float*)d_in[4];
    const float* eb2 = (const float*)d_in[5];
    const float* nw1 = (const float*)d_in[6];
    const float* nb1 = (const float*)d_in[7];
    const float* nw2 = (const float*)d_in[8];
    const float* nb2 = (const float*)d_in[9];
    float* x = (float*)d_out;

    const int SM_PROJ = (16384 + 2560) * 4;           // 75776
    const int SM_AGG  = (16384 + 4096) * 4;           // 81920
    const int SM_NODE = (16384 + 2560 + 2560) * 4;    // 86016
    cudaFuncSetAttribute(k_proj, cudaFuncAttributeMaxDynamicSharedMemorySize, SM_PROJ);
    cudaFuncSetAttribute(k_agg,  cudaFuncAttributeMaxDynamicSharedMemorySize, SM_AGG);
    cudaFuncSetAttribute(k_node, cudaFuncAttributeMaxDynamicSharedMemorySize, SM_NODE);

    k_setup_adj<<<1024, 256>>>(adj);
    k_rowsum<<<128, 256>>>(adj);
    k_wc<<<dim3(8, 3), 128>>>(ew2, eb2, nw1);
    cudaMemcpyAsync(x, nf, (size_t)BN * D_ * sizeof(float), cudaMemcpyDeviceToDevice, 0);

    for (int l = 0; l < L_; l++) {
        k_proj<<<dim3(64, 3), 128, SM_PROJ>>>(x, ew1, nw1, eb1, nb1, l);
        k_agg<<<dim3(64, 2), 128, SM_AGG>>>();
        k_node<<<64, 128, SM_NODE>>>(x, nw2, nb2, l);
    }
}